// round 4
// baseline (speedup 1.0000x reference)
#include <cuda_runtime.h>
#include <math.h>

// Problem constants
#define Bb 256
#define Tt 512
#define Ii 64
#define Hh 128
#define GH 512          // 4*H
#define NB 4            // batch samples per recurrence CTA
#define RS 416          // Whh rows resident in smem (rest streamed from L2)

typedef unsigned long long ull;

// ---------------- scratch (device globals; no cudaMalloc allowed) ----------
__device__ float g_xg[2 * Bb * Tt * GH];     // [dir][b][t][4H]  (536 MB)
__device__ float g_h0[Bb * Tt * 2 * Hh];     // layer0 output [b][t][2H]
__device__ float g_h1[Bb * Tt * 2 * Hh];     // layer1 output [b][t][2H]

// ---------------- f32x2 helpers (packed fp32 FMA, sm_100+) -----------------
__device__ __forceinline__ ull pk2(float x, float y) {
    ull r; asm("mov.b64 %0, {%1, %2};" : "=l"(r) : "f"(x), "f"(y)); return r;
}
__device__ __forceinline__ void fma2(ull& d, ull a, ull b) {
    asm("fma.rn.f32x2 %0, %1, %2, %0;" : "+l"(d) : "l"(a), "l"(b));
}
__device__ __forceinline__ void unpk2(ull v, float& x, float& y) {
    asm("mov.b64 {%0, %1}, %2;" : "=f"(x), "=f"(y) : "l"(v));
}
__device__ __forceinline__ float f4c(const float4 v, int i) {
    return i == 0 ? v.x : i == 1 ? v.y : i == 2 ? v.z : v.w;
}
__device__ __forceinline__ float sigf(float x) {
    return 1.0f / (1.0f + __expf(-x));
}

// ---------------- xg GEMM: Y[dir][m][n] = X[m,:]·W[n,:] + bih[n] + bhh[n] --
// X: [M,K] row-major, W: [512,K] row-major. M = B*T. Tile 64x64, BK=32.
__global__ void __launch_bounds__(256) xg_gemm(
    const float* __restrict__ X0, int layer, int K,
    const float* __restrict__ W0, const float* __restrict__ W1,
    const float* __restrict__ bi0, const float* __restrict__ bh0,
    const float* __restrict__ bi1, const float* __restrict__ bh1)
{
    const int M = Bb * Tt;
    __shared__ float Xs[32][68];   // [k][m], stride 68 floats (16B-aligned rows)
    __shared__ float Ws[32][68];   // [k][n]
    const float* X  = layer ? g_h0 : X0;
    const int dir   = blockIdx.z;
    const float* W  = dir ? W1 : W0;
    const float* bi = dir ? bi1 : bi0;
    const float* bh = dir ? bh1 : bh0;
    const int m0 = blockIdx.x * 64;
    const int n0 = blockIdx.y * 64;
    const int tid = threadIdx.x;
    const int tx = tid & 15, ty = tid >> 4;
    const int lk = tid & 31, lr = tid >> 5;

    ull acc[4][2];
#pragma unroll
    for (int i = 0; i < 4; i++) { acc[i][0] = 0ull; acc[i][1] = 0ull; }

    for (int kb = 0; kb < K; kb += 32) {
#pragma unroll
        for (int r = 0; r < 64; r += 8) {
            Xs[lk][r + lr] = X[(size_t)(m0 + r + lr) * K + kb + lk];
            Ws[lk][r + lr] = W[(size_t)(n0 + r + lr) * K + kb + lk];
        }
        __syncthreads();
#pragma unroll
        for (int k = 0; k < 32; ++k) {
            float4 av = *(const float4*)&Xs[k][ty * 4];
            float4 bv = *(const float4*)&Ws[k][tx * 4];
            ull b01 = pk2(bv.x, bv.y), b23 = pk2(bv.z, bv.w);
            ull a;
            a = pk2(av.x, av.x); fma2(acc[0][0], a, b01); fma2(acc[0][1], a, b23);
            a = pk2(av.y, av.y); fma2(acc[1][0], a, b01); fma2(acc[1][1], a, b23);
            a = pk2(av.z, av.z); fma2(acc[2][0], a, b01); fma2(acc[2][1], a, b23);
            a = pk2(av.w, av.w); fma2(acc[3][0], a, b01); fma2(acc[3][1], a, b23);
        }
        __syncthreads();
    }

    const int n = n0 + tx * 4;
    float bs0 = bi[n]     + bh[n];
    float bs1 = bi[n + 1] + bh[n + 1];
    float bs2 = bi[n + 2] + bh[n + 2];
    float bs3 = bi[n + 3] + bh[n + 3];
#pragma unroll
    for (int i = 0; i < 4; i++) {
        float v0, v1, v2, v3;
        unpk2(acc[i][0], v0, v1);
        unpk2(acc[i][1], v2, v3);
        size_t m = (size_t)(m0 + ty * 4 + i);
        float* y = g_xg + (size_t)dir * M * GH + m * GH + n;
        y[0] = v0 + bs0; y[1] = v1 + bs1; y[2] = v2 + bs2; y[3] = v3 + bs3;
    }
}

// ---------------- recurrence inner GEMM: 2 gate rows x 4 batches ----------
__device__ __forceinline__ void rec_dot(
    const float* __restrict__ wA, const float* __restrict__ wB,
    const float* __restrict__ hsp,
    ull& aA01, ull& aA23, ull& aB01, ull& aB23)
{
#pragma unroll 8
    for (int k = 0; k < Hh; k += 4) {
        float4 wa = *(const float4*)(wA + k);
        float4 wb = *(const float4*)(wB + k);
#pragma unroll
        for (int kk = 0; kk < 4; ++kk) {
            float4 hv = *(const float4*)(hsp + 4 * (k + kk));   // hs[k][b0..b3]
            ull h01 = pk2(hv.x, hv.y), h23 = pk2(hv.z, hv.w);
            float wav = f4c(wa, kk), wbv = f4c(wb, kk);
            ull a2 = pk2(wav, wav), b2 = pk2(wbv, wbv);
            fma2(aA01, a2, h01); fma2(aA23, a2, h23);
            fma2(aB01, b2, h01); fma2(aB23, b2, h23);
        }
    }
}

// ---------------- LSTM recurrence: one CTA = (direction, 4 batch samples) --
// smem: Whh rows [0,RS) (213 KB) + h[k][b] (2 KB) + gates G[b][4H] (8 KB)
__global__ void __launch_bounds__(256, 1) lstm_rec(
    int layer,
    const float* __restrict__ Wf, const float* __restrict__ Wr)
{
    extern __shared__ float sm[];
    float* sW = sm;                       // RS*128 floats
    float* hs = sm + RS * Hh;             // [128][NB]
    float* Gs = hs + NB * Hh;             // [NB][512]

    const int dir = blockIdx.y;
    const int b0  = blockIdx.x * NB;
    const float* Whh = dir ? Wr : Wf;
    float* hout = layer ? g_h1 : g_h0;
    const float* xg = g_xg + (size_t)dir * Bb * Tt * GH;
    const int tid = threadIdx.x;

    // load Whh rows [0,RS) into smem, zero h
    {
        const float4* src = (const float4*)Whh;
        float4* dst = (float4*)sW;
        for (int i = tid; i < RS * Hh / 4; i += 256) dst[i] = src[i];
        for (int i = tid; i < NB * Hh; i += 256) hs[i] = 0.f;
    }
    float c0 = 0.f, c1 = 0.f;             // cell state in registers
    const int rowA = tid;                 // gate row (always in smem)
    const int rowB = tid + 256;           // gate row (smem if < RS, else L2)
    const float* wA  = sW + rowA * Hh;
    const float* wBs = sW + rowB * Hh;
    const float* wBg = Whh + (size_t)rowB * Hh;
    const bool bglb = (rowB >= RS);       // uniform per warp (RS=416, 160=32*5)
    const int bu = tid >> 7, ju = tid & 127;
    __syncthreads();

    const size_t TG = (size_t)Tt * GH;
    for (int s = 0; s < Tt; ++s) {
        const int t = dir ? (Tt - 1 - s) : s;
        const size_t xb = (size_t)b0 * TG + (size_t)t * GH;
        // prefetch xg (consumed after the GEMM so latency is hidden)
        float xA0 = xg[xb + rowA];
        float xA1 = xg[xb + TG + rowA];
        float xA2 = xg[xb + 2 * TG + rowA];
        float xA3 = xg[xb + 3 * TG + rowA];
        float xB0 = xg[xb + rowB];
        float xB1 = xg[xb + TG + rowB];
        float xB2 = xg[xb + 2 * TG + rowB];
        float xB3 = xg[xb + 3 * TG + rowB];

        ull aA01 = 0, aA23 = 0, aB01 = 0, aB23 = 0;
        if (!bglb) rec_dot(wA, wBs, hs, aA01, aA23, aB01, aB23);
        else       rec_dot(wA, wBg, hs, aA01, aA23, aB01, aB23);

        float a0, a1, a2, a3;
        unpk2(aA01, a0, a1); unpk2(aA23, a2, a3);
        Gs[rowA]          = a0 + xA0;
        Gs[GH + rowA]     = a1 + xA1;
        Gs[2 * GH + rowA] = a2 + xA2;
        Gs[3 * GH + rowA] = a3 + xA3;
        unpk2(aB01, a0, a1); unpk2(aB23, a2, a3);
        Gs[rowB]          = a0 + xB0;
        Gs[GH + rowB]     = a1 + xB1;
        Gs[2 * GH + rowB] = a2 + xB2;
        Gs[3 * GH + rowB] = a3 + xB3;
        __syncthreads();

        // elementwise update: this thread owns (bu, ju) and (bu+2, ju)
        {
            const float* G = Gs + bu * GH;
            float ii = G[ju], ff = G[Hh + ju], gg = G[2 * Hh + ju], oo = G[3 * Hh + ju];
            c0 = sigf(ff) * c0 + sigf(ii) * tanhf(gg);
            float h = sigf(oo) * tanhf(c0);
            hs[ju * NB + bu] = h;
            hout[((size_t)(b0 + bu) * Tt + t) * (2 * Hh) + dir * Hh + ju] = h;
        }
        {
            const int b = bu + 2;
            const float* G = Gs + b * GH;
            float ii = G[ju], ff = G[Hh + ju], gg = G[2 * Hh + ju], oo = G[3 * Hh + ju];
            c1 = sigf(ff) * c1 + sigf(ii) * tanhf(gg);
            float h = sigf(oo) * tanhf(c1);
            hs[ju * NB + b] = h;
            hout[((size_t)(b0 + b) * Tt + t) * (2 * Hh) + dir * Hh + ju] = h;
        }
        __syncthreads();
    }
}

// ---------------- FC head: out[b] = relu(last@fc1^T+b1) @ fc2^T + b2 -------
__global__ void __launch_bounds__(128) fc_head(
    const float* __restrict__ fc1w, const float* __restrict__ fc1b,
    const float* __restrict__ fc2w, const float* __restrict__ fc2b,
    float* __restrict__ out)
{
    __shared__ float last[2 * Hh];
    __shared__ float red[Hh];
    const int b = blockIdx.x, tid = threadIdx.x;
    const float* src = g_h1 + ((size_t)b * Tt + (Tt - 1)) * (2 * Hh);
    last[tid] = src[tid];
    last[tid + Hh] = src[tid + Hh];
    __syncthreads();
    float s = fc1b[tid];
    const float* wr = fc1w + tid * (2 * Hh);
#pragma unroll 8
    for (int k = 0; k < 2 * Hh; ++k) s += wr[k] * last[k];
    red[tid] = fmaxf(s, 0.f) * fc2w[tid];
    __syncthreads();
    for (int st = 64; st > 0; st >>= 1) {
        if (tid < st) red[tid] += red[tid + st];
        __syncthreads();
    }
    if (tid == 0) out[b] = red[0] + fc2b[0];
}

// ---------------- launch ---------------------------------------------------
extern "C" void kernel_launch(void* const* d_in, const int* in_sizes, int n_in,
                              void* d_out, int out_size)
{
    (void)in_sizes; (void)n_in; (void)out_size;
    const float* x     = (const float*)d_in[0];
    const float* Wih0  = (const float*)d_in[1];
    const float* Whh0  = (const float*)d_in[2];
    const float* bih0  = (const float*)d_in[3];
    const float* bhh0  = (const float*)d_in[4];
    const float* Wih0r = (const float*)d_in[5];
    const float* Whh0r = (const float*)d_in[6];
    const float* bih0r = (const float*)d_in[7];
    const float* bhh0r = (const float*)d_in[8];
    const float* Wih1  = (const float*)d_in[9];
    const float* Whh1  = (const float*)d_in[10];
    const float* bih1  = (const float*)d_in[11];
    const float* bhh1  = (const float*)d_in[12];
    const float* Wih1r = (const float*)d_in[13];
    const float* Whh1r = (const float*)d_in[14];
    const float* bih1r = (const float*)d_in[15];
    const float* bhh1r = (const float*)d_in[16];
    const float* fc1w  = (const float*)d_in[17];
    const float* fc1b  = (const float*)d_in[18];
    const float* fc2w  = (const float*)d_in[19];
    const float* fc2b  = (const float*)d_in[20];
    float* out = (float*)d_out;

    const int SMEM = (RS * Hh + NB * Hh + NB * GH) * 4;   // 223232 B
    cudaFuncSetAttribute(lstm_rec, cudaFuncAttributeMaxDynamicSharedMemorySize, SMEM);

    dim3 gg(Bb * Tt / 64, GH / 64, 2);
    dim3 gr(Bb / NB, 2);

    // layer 0
    xg_gemm<<<gg, 256>>>(x, 0, Ii, Wih0, Wih0r, bih0, bhh0, bih0r, bhh0r);
    lstm_rec<<<gr, 256, SMEM>>>(0, Whh0, Whh0r);
    // layer 1 (input = g_h0, K = 256)
    xg_gemm<<<gg, 256>>>(x, 1, 2 * Hh, Wih1, Wih1r, bih1, bhh1, bih1r, bhh1r);
    lstm_rec<<<gr, 256, SMEM>>>(1, Whh1, Whh1r);
    // head
    fc_head<<<Bb, Hh>>>(fc1w, fc1b, fc2w, fc2b, out);
}

// round 5
// speedup vs baseline: 3.0434x; 3.0434x over previous
#include <cuda_runtime.h>
#include <math.h>

// Problem constants
#define Bb 256
#define Tt 512
#define Ii 64
#define Hh 128
#define GH 512          // 4*H
#define NB 4            // batch samples per recurrence CTA
#define RS 416          // Whh rows resident in smem (rest streamed from L2)
#define WSTR 132        // padded row stride (floats): 132 mod 32 = 4 -> conflict-free LDS.128

typedef unsigned long long ull;

// ---------------- scratch (device globals; no cudaMalloc allowed) ----------
__device__ float g_xg[2 * Bb * Tt * GH];     // [dir][b][t][4H]
__device__ float g_h0[Bb * Tt * 2 * Hh];     // layer0 output [b][t][2H]
__device__ float g_h1[Bb * Tt * 2 * Hh];     // layer1 output [b][t][2H]

// ---------------- f32x2 helpers (packed fp32 FMA, sm_100+) -----------------
__device__ __forceinline__ ull pk2(float x, float y) {
    ull r; asm("mov.b64 %0, {%1, %2};" : "=l"(r) : "f"(x), "f"(y)); return r;
}
__device__ __forceinline__ void fma2(ull& d, ull a, ull b) {
    asm("fma.rn.f32x2 %0, %1, %2, %0;" : "+l"(d) : "l"(a), "l"(b));
}
__device__ __forceinline__ void unpk2(ull v, float& x, float& y) {
    asm("mov.b64 {%0, %1}, %2;" : "=f"(x), "=f"(y) : "l"(v));
}
__device__ __forceinline__ float f4c(const float4 v, int i) {
    return i == 0 ? v.x : i == 1 ? v.y : i == 2 ? v.z : v.w;
}
__device__ __forceinline__ float sigf(float x) {
    return 1.0f / (1.0f + __expf(-x));
}

// ---------------- xg GEMM: Y[dir][m][n] = X[m,:]·W[n,:] + bih[n] + bhh[n] --
// X: [M,K] row-major, W: [512,K] row-major. M = B*T.
// CTA tile 64(m) x 128(n), BK=32. Thread tile 4(m) x 8(n) (two 64-wide halves).
__global__ void __launch_bounds__(256) xg_gemm(
    const float* __restrict__ X0, int layer, int K,
    const float* __restrict__ W0, const float* __restrict__ W1,
    const float* __restrict__ bi0, const float* __restrict__ bh0,
    const float* __restrict__ bi1, const float* __restrict__ bh1)
{
    const int M = Bb * Tt;
    __shared__ float Xs[32][68];    // [k][m]
    __shared__ float Ws[32][132];   // [k][n], padded stride
    const float* X  = layer ? g_h0 : X0;
    const int dir   = blockIdx.z;
    const float* W  = dir ? W1 : W0;
    const float* bi = dir ? bi1 : bi0;
    const float* bh = dir ? bh1 : bh0;
    const int m0 = blockIdx.x * 64;
    const int n0 = blockIdx.y * 128;
    const int tid = threadIdx.x;
    const int tx = tid & 15, ty = tid >> 4;
    const int lk = tid & 31, lr = tid >> 5;

    ull acc[4][4];
#pragma unroll
    for (int i = 0; i < 4; i++)
#pragma unroll
        for (int j = 0; j < 4; j++) acc[i][j] = 0ull;

    for (int kb = 0; kb < K; kb += 32) {
#pragma unroll
        for (int r = 0; r < 64; r += 8)
            Xs[lk][r + lr] = X[(size_t)(m0 + r + lr) * K + kb + lk];
#pragma unroll
        for (int r = 0; r < 128; r += 8)
            Ws[lk][r + lr] = W[(size_t)(n0 + r + lr) * K + kb + lk];
        __syncthreads();
#pragma unroll
        for (int k = 0; k < 32; ++k) {
            float4 av = *(const float4*)&Xs[k][ty * 4];
            float4 b0 = *(const float4*)&Ws[k][tx * 4];
            float4 b1 = *(const float4*)&Ws[k][64 + tx * 4];
            ull p0 = pk2(b0.x, b0.y), p1 = pk2(b0.z, b0.w);
            ull p2 = pk2(b1.x, b1.y), p3 = pk2(b1.z, b1.w);
            ull a;
            a = pk2(av.x, av.x);
            fma2(acc[0][0], a, p0); fma2(acc[0][1], a, p1);
            fma2(acc[0][2], a, p2); fma2(acc[0][3], a, p3);
            a = pk2(av.y, av.y);
            fma2(acc[1][0], a, p0); fma2(acc[1][1], a, p1);
            fma2(acc[1][2], a, p2); fma2(acc[1][3], a, p3);
            a = pk2(av.z, av.z);
            fma2(acc[2][0], a, p0); fma2(acc[2][1], a, p1);
            fma2(acc[2][2], a, p2); fma2(acc[2][3], a, p3);
            a = pk2(av.w, av.w);
            fma2(acc[3][0], a, p0); fma2(acc[3][1], a, p1);
            fma2(acc[3][2], a, p2); fma2(acc[3][3], a, p3);
        }
        __syncthreads();
    }

    const int n = n0 + tx * 4;
    float bsA[4], bsB[4];
#pragma unroll
    for (int j = 0; j < 4; j++) {
        bsA[j] = bi[n + j]      + bh[n + j];
        bsB[j] = bi[n + 64 + j] + bh[n + 64 + j];
    }
#pragma unroll
    for (int i = 0; i < 4; i++) {
        float v0, v1, v2, v3;
        size_t m = (size_t)(m0 + ty * 4 + i);
        float* y = g_xg + (size_t)dir * M * GH + m * GH;
        unpk2(acc[i][0], v0, v1); unpk2(acc[i][1], v2, v3);
        y[n]     = v0 + bsA[0]; y[n + 1] = v1 + bsA[1];
        y[n + 2] = v2 + bsA[2]; y[n + 3] = v3 + bsA[3];
        unpk2(acc[i][2], v0, v1); unpk2(acc[i][3], v2, v3);
        y[n + 64] = v0 + bsB[0]; y[n + 65] = v1 + bsB[1];
        y[n + 66] = v2 + bsB[2]; y[n + 67] = v3 + bsB[3];
    }
}

// ---------------- recurrence inner GEMM: 2 gate rows x 4 batches ----------
__device__ __forceinline__ void rec_dot(
    const float* __restrict__ wA, const float* __restrict__ wB,
    const float* __restrict__ hsp,
    ull& aA01, ull& aA23, ull& aB01, ull& aB23)
{
#pragma unroll 8
    for (int k = 0; k < Hh; k += 4) {
        float4 wa = *(const float4*)(wA + k);
        float4 wb = *(const float4*)(wB + k);
#pragma unroll
        for (int kk = 0; kk < 4; ++kk) {
            float4 hv = *(const float4*)(hsp + 4 * (k + kk));   // hs[k][b0..b3]
            ull h01 = pk2(hv.x, hv.y), h23 = pk2(hv.z, hv.w);
            float wav = f4c(wa, kk), wbv = f4c(wb, kk);
            ull a2 = pk2(wav, wav), b2 = pk2(wbv, wbv);
            fma2(aA01, a2, h01); fma2(aA23, a2, h23);
            fma2(aB01, b2, h01); fma2(aB23, b2, h23);
        }
    }
}

// ---------------- LSTM recurrence: one CTA = (direction, 4 batch samples) --
// smem: Whh rows [0,RS) padded to WSTR (214.5 KB) + h[k][b] (2 KB) + G (8 KB)
__global__ void __launch_bounds__(256, 1) lstm_rec(
    int layer,
    const float* __restrict__ Wf, const float* __restrict__ Wr)
{
    extern __shared__ float sm[];
    float* sW = sm;                       // RS * WSTR floats
    float* hs = sm + RS * WSTR;           // [128][NB]
    float* Gs = hs + NB * Hh;             // [NB][512]

    const int dir = blockIdx.y;
    const int b0  = blockIdx.x * NB;
    const float* Whh = dir ? Wr : Wf;
    float* hout = layer ? g_h1 : g_h0;
    const float* xg = g_xg + (size_t)dir * Bb * Tt * GH;
    const int tid = threadIdx.x;

    // load Whh rows [0,RS) into padded smem, zero h
    {
        const float4* src = (const float4*)Whh;
        for (int i = tid; i < RS * (Hh / 4); i += 256) {
            int r = i >> 5, c = i & 31;                // 32 float4 per row
            *(float4*)(sW + r * WSTR + c * 4) = src[i];
        }
        for (int i = tid; i < NB * Hh; i += 256) hs[i] = 0.f;
    }
    float c0 = 0.f, c1 = 0.f;             // cell state in registers
    const int rowA = tid;                 // gate row (always in smem)
    const int rowB = tid + 256;           // gate row (smem if < RS, else L2)
    const float* wA  = sW + rowA * WSTR;
    const float* wBs = sW + rowB * WSTR;
    const float* wBg = Whh + (size_t)rowB * Hh;
    const bool bglb = (rowB >= RS);       // warp-uniform (RS-256 = 160 = 5*32)
    const int bu = tid >> 7, ju = tid & 127;
    __syncthreads();

    const size_t TG = (size_t)Tt * GH;
    for (int s = 0; s < Tt; ++s) {
        const int t = dir ? (Tt - 1 - s) : s;
        const size_t xb = (size_t)b0 * TG + (size_t)t * GH;
        // prefetch xg (consumed after the GEMM so latency is hidden)
        float xA0 = xg[xb + rowA];
        float xA1 = xg[xb + TG + rowA];
        float xA2 = xg[xb + 2 * TG + rowA];
        float xA3 = xg[xb + 3 * TG + rowA];
        float xB0 = xg[xb + rowB];
        float xB1 = xg[xb + TG + rowB];
        float xB2 = xg[xb + 2 * TG + rowB];
        float xB3 = xg[xb + 3 * TG + rowB];

        ull aA01 = 0, aA23 = 0, aB01 = 0, aB23 = 0;
        if (!bglb) rec_dot(wA, wBs, hs, aA01, aA23, aB01, aB23);
        else       rec_dot(wA, wBg, hs, aA01, aA23, aB01, aB23);

        float a0, a1, a2, a3;
        unpk2(aA01, a0, a1); unpk2(aA23, a2, a3);
        Gs[rowA]          = a0 + xA0;
        Gs[GH + rowA]     = a1 + xA1;
        Gs[2 * GH + rowA] = a2 + xA2;
        Gs[3 * GH + rowA] = a3 + xA3;
        unpk2(aB01, a0, a1); unpk2(aB23, a2, a3);
        Gs[rowB]          = a0 + xB0;
        Gs[GH + rowB]     = a1 + xB1;
        Gs[2 * GH + rowB] = a2 + xB2;
        Gs[3 * GH + rowB] = a3 + xB3;
        __syncthreads();

        // elementwise update: this thread owns (bu, ju) and (bu+2, ju)
        {
            const float* G = Gs + bu * GH;
            float ii = G[ju], ff = G[Hh + ju], gg = G[2 * Hh + ju], oo = G[3 * Hh + ju];
            c0 = sigf(ff) * c0 + sigf(ii) * tanhf(gg);
            float h = sigf(oo) * tanhf(c0);
            hs[ju * NB + bu] = h;
            hout[((size_t)(b0 + bu) * Tt + t) * (2 * Hh) + dir * Hh + ju] = h;
        }
        {
            const int b = bu + 2;
            const float* G = Gs + b * GH;
            float ii = G[ju], ff = G[Hh + ju], gg = G[2 * Hh + ju], oo = G[3 * Hh + ju];
            c1 = sigf(ff) * c1 + sigf(ii) * tanhf(gg);
            float h = sigf(oo) * tanhf(c1);
            hs[ju * NB + b] = h;
            hout[((size_t)(b0 + b) * Tt + t) * (2 * Hh) + dir * Hh + ju] = h;
        }
        __syncthreads();
    }
}

// ---------------- FC head: out[b] = relu(last@fc1^T+b1) @ fc2^T + b2 -------
__global__ void __launch_bounds__(128) fc_head(
    const float* __restrict__ fc1w, const float* __restrict__ fc1b,
    const float* __restrict__ fc2w, const float* __restrict__ fc2b,
    float* __restrict__ out)
{
    __shared__ float last[2 * Hh];
    __shared__ float red[Hh];
    const int b = blockIdx.x, tid = threadIdx.x;
    const float* src = g_h1 + ((size_t)b * Tt + (Tt - 1)) * (2 * Hh);
    last[tid] = src[tid];
    last[tid + Hh] = src[tid + Hh];
    __syncthreads();
    float s = fc1b[tid];
    const float* wr = fc1w + tid * (2 * Hh);
#pragma unroll 8
    for (int k = 0; k < 2 * Hh; ++k) s += wr[k] * last[k];
    red[tid] = fmaxf(s, 0.f) * fc2w[tid];
    __syncthreads();
    for (int st = 64; st > 0; st >>= 1) {
        if (tid < st) red[tid] += red[tid + st];
        __syncthreads();
    }
    if (tid == 0) out[b] = red[0] + fc2b[0];
}

// ---------------- launch ---------------------------------------------------
extern "C" void kernel_launch(void* const* d_in, const int* in_sizes, int n_in,
                              void* d_out, int out_size)
{
    (void)in_sizes; (void)n_in; (void)out_size;
    const float* x     = (const float*)d_in[0];
    const float* Wih0  = (const float*)d_in[1];
    const float* Whh0  = (const float*)d_in[2];
    const float* bih0  = (const float*)d_in[3];
    const float* bhh0  = (const float*)d_in[4];
    const float* Wih0r = (const float*)d_in[5];
    const float* Whh0r = (const float*)d_in[6];
    const float* bih0r = (const float*)d_in[7];
    const float* bhh0r = (const float*)d_in[8];
    const float* Wih1  = (const float*)d_in[9];
    const float* Whh1  = (const float*)d_in[10];
    const float* bih1  = (const float*)d_in[11];
    const float* bhh1  = (const float*)d_in[12];
    const float* Wih1r = (const float*)d_in[13];
    const float* Whh1r = (const float*)d_in[14];
    const float* bih1r = (const float*)d_in[15];
    const float* bhh1r = (const float*)d_in[16];
    const float* fc1w  = (const float*)d_in[17];
    const float* fc1b  = (const float*)d_in[18];
    const float* fc2w  = (const float*)d_in[19];
    const float* fc2b  = (const float*)d_in[20];
    float* out = (float*)d_out;

    const int SMEM = (RS * WSTR + NB * Hh + NB * GH) * 4;   // 229,888 B
    cudaFuncSetAttribute(lstm_rec, cudaFuncAttributeMaxDynamicSharedMemorySize, SMEM);

    dim3 gg(Bb * Tt / 64, GH / 128, 2);
    dim3 gr(Bb / NB, 2);

    // layer 0
    xg_gemm<<<gg, 256>>>(x, 0, Ii, Wih0, Wih0r, bih0, bhh0, bih0r, bhh0r);
    lstm_rec<<<gr, 256, SMEM>>>(0, Whh0, Whh0r);
    // layer 1 (input = g_h0, K = 256)
    xg_gemm<<<gg, 256>>>(x, 1, 2 * Hh, Wih1, Wih1r, bih1, bhh1, bih1r, bhh1r);
    lstm_rec<<<gr, 256, SMEM>>>(1, Whh1, Whh1r);
    // head
    fc_head<<<Bb, Hh>>>(fc1w, fc1b, fc2w, fc2b, out);
}

// round 6
// speedup vs baseline: 3.6648x; 1.2042x over previous
#include <cuda_runtime.h>
#include <math.h>

// Problem constants
#define Bb 256
#define Tt 512
#define Ii 64
#define Hh 128
#define GH 512          // 4*H
#define NB 4            // batch samples per recurrence CTA
#define KS 96           // weight cols kept in smem (cols 96..127 live in regs)
#define WSTR 100        // padded smem row stride (words): 100/4=25 odd -> conflict-free LDS.128

typedef unsigned long long ull;

// ---------------- scratch (device globals; no cudaMalloc allowed) ----------
__device__ float g_xg[2 * Bb * Tt * GH];     // [dir][b][t][4H]
__device__ float g_h0[Bb * Tt * 2 * Hh];     // layer0 output [b][t][2H]
__device__ float g_h1[Bb * Tt * 2 * Hh];     // layer1 output [b][t][2H]

// ---------------- f32x2 helpers (packed fp32 FMA, sm_100+) -----------------
__device__ __forceinline__ ull pk2(float x, float y) {
    ull r; asm("mov.b64 %0, {%1, %2};" : "=l"(r) : "f"(x), "f"(y)); return r;
}
__device__ __forceinline__ void fma2(ull& d, ull a, ull b) {
    asm("fma.rn.f32x2 %0, %1, %2, %0;" : "+l"(d) : "l"(a), "l"(b));
}
__device__ __forceinline__ void unpk2(ull v, float& x, float& y) {
    asm("mov.b64 {%0, %1}, %2;" : "=f"(x), "=f"(y) : "l"(v));
}
__device__ __forceinline__ float f4c(const float4 v, int i) {
    return i == 0 ? v.x : i == 1 ? v.y : i == 2 ? v.z : v.w;
}
__device__ __forceinline__ float sigf(float x) {
    return 1.0f / (1.0f + __expf(-x));
}

// ---------------- xg GEMM: Y[dir][m][n] = X[m,:]·W[n,:] + bih[n] + bhh[n] --
// X: [M,K] row-major, W: [512,K] row-major. M = B*T.
// CTA tile 64(m) x 128(n), BK=32. Thread tile 4(m) x 8(n) (two 64-wide halves).
__global__ void __launch_bounds__(256) xg_gemm(
    const float* __restrict__ X0, int layer, int K,
    const float* __restrict__ W0, const float* __restrict__ W1,
    const float* __restrict__ bi0, const float* __restrict__ bh0,
    const float* __restrict__ bi1, const float* __restrict__ bh1)
{
    const int M = Bb * Tt;
    __shared__ float Xs[32][68];    // [k][m]
    __shared__ float Ws[32][132];   // [k][n], padded stride
    const float* X  = layer ? g_h0 : X0;
    const int dir   = blockIdx.z;
    const float* W  = dir ? W1 : W0;
    const float* bi = dir ? bi1 : bi0;
    const float* bh = dir ? bh1 : bh0;
    const int m0 = blockIdx.x * 64;
    const int n0 = blockIdx.y * 128;
    const int tid = threadIdx.x;
    const int tx = tid & 15, ty = tid >> 4;
    const int lk = tid & 31, lr = tid >> 5;

    ull acc[4][4];
#pragma unroll
    for (int i = 0; i < 4; i++)
#pragma unroll
        for (int j = 0; j < 4; j++) acc[i][j] = 0ull;

    for (int kb = 0; kb < K; kb += 32) {
#pragma unroll
        for (int r = 0; r < 64; r += 8)
            Xs[lk][r + lr] = X[(size_t)(m0 + r + lr) * K + kb + lk];
#pragma unroll
        for (int r = 0; r < 128; r += 8)
            Ws[lk][r + lr] = W[(size_t)(n0 + r + lr) * K + kb + lk];
        __syncthreads();
#pragma unroll
        for (int k = 0; k < 32; ++k) {
            float4 av = *(const float4*)&Xs[k][ty * 4];
            float4 b0 = *(const float4*)&Ws[k][tx * 4];
            float4 b1 = *(const float4*)&Ws[k][64 + tx * 4];
            ull p0 = pk2(b0.x, b0.y), p1 = pk2(b0.z, b0.w);
            ull p2 = pk2(b1.x, b1.y), p3 = pk2(b1.z, b1.w);
            ull a;
            a = pk2(av.x, av.x);
            fma2(acc[0][0], a, p0); fma2(acc[0][1], a, p1);
            fma2(acc[0][2], a, p2); fma2(acc[0][3], a, p3);
            a = pk2(av.y, av.y);
            fma2(acc[1][0], a, p0); fma2(acc[1][1], a, p1);
            fma2(acc[1][2], a, p2); fma2(acc[1][3], a, p3);
            a = pk2(av.z, av.z);
            fma2(acc[2][0], a, p0); fma2(acc[2][1], a, p1);
            fma2(acc[2][2], a, p2); fma2(acc[2][3], a, p3);
            a = pk2(av.w, av.w);
            fma2(acc[3][0], a, p0); fma2(acc[3][1], a, p1);
            fma2(acc[3][2], a, p2); fma2(acc[3][3], a, p3);
        }
        __syncthreads();
    }

    const int n = n0 + tx * 4;
    float bsA[4], bsB[4];
#pragma unroll
    for (int j = 0; j < 4; j++) {
        bsA[j] = bi[n + j]      + bh[n + j];
        bsB[j] = bi[n + 64 + j] + bh[n + 64 + j];
    }
#pragma unroll
    for (int i = 0; i < 4; i++) {
        float v0, v1, v2, v3;
        size_t m = (size_t)(m0 + ty * 4 + i);
        float* y = g_xg + (size_t)dir * M * GH + m * GH;
        unpk2(acc[i][0], v0, v1); unpk2(acc[i][1], v2, v3);
        y[n]     = v0 + bsA[0]; y[n + 1] = v1 + bsA[1];
        y[n + 2] = v2 + bsA[2]; y[n + 3] = v3 + bsA[3];
        unpk2(acc[i][2], v0, v1); unpk2(acc[i][3], v2, v3);
        y[n + 64] = v0 + bsB[0]; y[n + 65] = v1 + bsB[1];
        y[n + 66] = v2 + bsB[2]; y[n + 67] = v3 + bsB[3];
    }
}

// ---------------- LSTM recurrence: one CTA = (direction, 4 batch samples) --
// 512 threads; thread tid owns gate row tid (of 512) for all NB batches.
// smem: all 512 weight rows, cols [0,96) @ stride 100 (204.8 KB)
//       + h[k][b] (2 KB) + gates G[b][4H] (8 KB). Cols [96,128) in registers.
__global__ void __launch_bounds__(512, 1) lstm_rec(
    int layer,
    const float* __restrict__ Wf, const float* __restrict__ Wr)
{
    extern __shared__ float sm[];
    float* sW = sm;                       // 512 * WSTR floats
    float* hs = sm + GH * WSTR;           // [128][NB]
    float* Gs = hs + NB * Hh;             // [NB][512]

    const int dir = blockIdx.y;
    const int b0  = blockIdx.x * NB;
    const float* Whh = dir ? Wr : Wf;
    float* hout = layer ? g_h1 : g_h0;
    const float* xg = g_xg + (size_t)dir * Bb * Tt * GH;
    const int tid  = threadIdx.x;
    const int lane = tid & 31, wid = tid >> 5;

    // --- load weights: cols [0,96) of every row into smem (coalesced by row),
    //     cols [96,128) of this thread's own row into registers ---
    {
        const float4* src = (const float4*)Whh;   // 32 float4 per row
        for (int r = wid; r < GH; r += 16)
            if (lane < 24)
                *(float4*)(sW + r * WSTR + lane * 4) = src[r * 32 + lane];
        for (int i = tid; i < NB * Hh; i += 512) hs[i] = 0.f;
    }
    float4 wreg[8];
    {
        const float4* src = (const float4*)(Whh + (size_t)tid * Hh);
#pragma unroll
        for (int j = 0; j < 8; ++j) wreg[j] = src[24 + j];
    }
    float c0 = 0.f;                       // cell state (one (b,j) per thread)
    const float* wrow = sW + tid * WSTR;
    const int bu = tid >> 7, ju = tid & 127;
    __syncthreads();

    const size_t TG = (size_t)Tt * GH;
    for (int s = 0; s < Tt; ++s) {
        const int t = dir ? (Tt - 1 - s) : s;
        const size_t xb = (size_t)b0 * TG + (size_t)t * GH + tid;
        // prefetch xg for this gate row, all 4 batches
        float x0 = xg[xb];
        float x1 = xg[xb + TG];
        float x2 = xg[xb + 2 * TG];
        float x3 = xg[xb + 3 * TG];

        ull a01 = 0, a23 = 0;             // (b0,b1) and (b2,b3) accumulators
#pragma unroll 6
        for (int k = 0; k < KS; k += 4) {
            float4 wv = *(const float4*)(wrow + k);
#pragma unroll
            for (int kk = 0; kk < 4; ++kk) {
                float4 hv = *(const float4*)(hs + 4 * (k + kk));
                ull h01 = pk2(hv.x, hv.y), h23 = pk2(hv.z, hv.w);
                float wv1 = f4c(wv, kk);
                ull a2 = pk2(wv1, wv1);
                fma2(a01, a2, h01); fma2(a23, a2, h23);
            }
        }
#pragma unroll
        for (int j = 0; j < 8; ++j) {
            float4 wv = wreg[j];
            const int k = KS + 4 * j;
#pragma unroll
            for (int kk = 0; kk < 4; ++kk) {
                float4 hv = *(const float4*)(hs + 4 * (k + kk));
                ull h01 = pk2(hv.x, hv.y), h23 = pk2(hv.z, hv.w);
                float wv1 = f4c(wv, kk);
                ull a2 = pk2(wv1, wv1);
                fma2(a01, a2, h01); fma2(a23, a2, h23);
            }
        }

        float a0, a1, a2f, a3f;
        unpk2(a01, a0, a1); unpk2(a23, a2f, a3f);
        Gs[tid]          = a0  + x0;
        Gs[GH + tid]     = a1  + x1;
        Gs[2 * GH + tid] = a2f + x2;
        Gs[3 * GH + tid] = a3f + x3;
        __syncthreads();

        // elementwise update: thread owns (bu, ju)
        {
            const float* G = Gs + bu * GH;
            float ii = G[ju], ff = G[Hh + ju], gg = G[2 * Hh + ju], oo = G[3 * Hh + ju];
            c0 = sigf(ff) * c0 + sigf(ii) * tanhf(gg);
            float h = sigf(oo) * tanhf(c0);
            hs[ju * NB + bu] = h;
            hout[((size_t)(b0 + bu) * Tt + t) * (2 * Hh) + dir * Hh + ju] = h;
        }
        __syncthreads();
    }
}

// ---------------- FC head: out[b] = relu(last@fc1^T+b1) @ fc2^T + b2 -------
__global__ void __launch_bounds__(128) fc_head(
    const float* __restrict__ fc1w, const float* __restrict__ fc1b,
    const float* __restrict__ fc2w, const float* __restrict__ fc2b,
    float* __restrict__ out)
{
    __shared__ float last[2 * Hh];
    __shared__ float red[Hh];
    const int b = blockIdx.x, tid = threadIdx.x;
    const float* src = g_h1 + ((size_t)b * Tt + (Tt - 1)) * (2 * Hh);
    last[tid] = src[tid];
    last[tid + Hh] = src[tid + Hh];
    __syncthreads();
    float s = fc1b[tid];
    const float* wr = fc1w + tid * (2 * Hh);
#pragma unroll 8
    for (int k = 0; k < 2 * Hh; ++k) s += wr[k] * last[k];
    red[tid] = fmaxf(s, 0.f) * fc2w[tid];
    __syncthreads();
    for (int st = 64; st > 0; st >>= 1) {
        if (tid < st) red[tid] += red[tid + st];
        __syncthreads();
    }
    if (tid == 0) out[b] = red[0] + fc2b[0];
}

// ---------------- launch ---------------------------------------------------
extern "C" void kernel_launch(void* const* d_in, const int* in_sizes, int n_in,
                              void* d_out, int out_size)
{
    (void)in_sizes; (void)n_in; (void)out_size;
    const float* x     = (const float*)d_in[0];
    const float* Wih0  = (const float*)d_in[1];
    const float* Whh0  = (const float*)d_in[2];
    const float* bih0  = (const float*)d_in[3];
    const float* bhh0  = (const float*)d_in[4];
    const float* Wih0r = (const float*)d_in[5];
    const float* Whh0r = (const float*)d_in[6];
    const float* bih0r = (const float*)d_in[7];
    const float* bhh0r = (const float*)d_in[8];
    const float* Wih1  = (const float*)d_in[9];
    const float* Whh1  = (const float*)d_in[10];
    const float* bih1  = (const float*)d_in[11];
    const float* bhh1  = (const float*)d_in[12];
    const float* Wih1r = (const float*)d_in[13];
    const float* Whh1r = (const float*)d_in[14];
    const float* bih1r = (const float*)d_in[15];
    const float* bhh1r = (const float*)d_in[16];
    const float* fc1w  = (const float*)d_in[17];
    const float* fc1b  = (const float*)d_in[18];
    const float* fc2w  = (const float*)d_in[19];
    const float* fc2b  = (const float*)d_in[20];
    float* out = (float*)d_out;

    const int SMEM = (GH * WSTR + NB * Hh + NB * GH) * 4;   // 215,040 B
    cudaFuncSetAttribute(lstm_rec, cudaFuncAttributeMaxDynamicSharedMemorySize, SMEM);

    dim3 gg(Bb * Tt / 64, GH / 128, 2);
    dim3 gr(Bb / NB, 2);

    // layer 0
    xg_gemm<<<gg, 256>>>(x, 0, Ii, Wih0, Wih0r, bih0, bhh0, bih0r, bhh0r);
    lstm_rec<<<gr, 512, SMEM>>>(0, Whh0, Whh0r);
    // layer 1 (input = g_h0, K = 256)
    xg_gemm<<<gg, 256>>>(x, 1, 2 * Hh, Wih1, Wih1r, bih1, bhh1, bih1r, bhh1r);
    lstm_rec<<<gr, 512, SMEM>>>(1, Whh1, Whh1r);
    // head
    fc_head<<<Bb, Hh>>>(fc1w, fc1b, fc2w, fc2b, out);
}

// round 7
// speedup vs baseline: 3.7963x; 1.0359x over previous
#include <cuda_runtime.h>
#include <math.h>

// Problem constants
#define Bb 256
#define Tt 512
#define Ii 64
#define Hh 128
#define GH 512          // 4*H
#define NB 4            // batch samples per recurrence CTA
#define KS 96           // weight cols kept in smem (cols 96..127 live in regs)
#define WSTR 100        // padded smem row stride (words): 25 quads -> conflict-free LDS.128

typedef unsigned long long ull;

// ---------------- scratch (device globals; no cudaMalloc allowed) ----------
__device__ float g_xg[2 * Bb * Tt * GH];     // [dir][b][t][4H]
__device__ float g_h0[Bb * Tt * 2 * Hh];     // layer0 output [b][t][2H]
__device__ float g_h1[Bb * Tt * 2 * Hh];     // layer1 output [b][t][2H]

// ---------------- f32x2 helpers (packed fp32 FMA, sm_100+) -----------------
__device__ __forceinline__ ull pk2(float x, float y) {
    ull r; asm("mov.b64 %0, {%1, %2};" : "=l"(r) : "f"(x), "f"(y)); return r;
}
__device__ __forceinline__ void fma2(ull& d, ull a, ull b) {
    asm("fma.rn.f32x2 %0, %1, %2, %0;" : "+l"(d) : "l"(a), "l"(b));
}
__device__ __forceinline__ ull add2(ull a, ull b) {
    ull r; asm("add.rn.f32x2 %0, %1, %2;" : "=l"(r) : "l"(a), "l"(b)); return r;
}
__device__ __forceinline__ void unpk2(ull v, float& x, float& y) {
    asm("mov.b64 {%0, %1}, %2;" : "=f"(x), "=f"(y) : "l"(v));
}
__device__ __forceinline__ float f4c(const float4 v, int i) {
    return i == 0 ? v.x : i == 1 ? v.y : i == 2 ? v.z : v.w;
}
// fast activations: __expf + MUFU.RCP; rel err ~1e-6 (budget 1e-3)
__device__ __forceinline__ float sigf(float x) {
    float e = __expf(-x);
    return __fdividef(1.0f, 1.0f + e);
}
__device__ __forceinline__ float tanhfast(float x) {
    float e = __expf(-2.0f * x);
    return __fdividef(1.0f - e, 1.0f + e);
}

// ---------------- xg GEMM v2: Y[dir][m][n] = X[m,:]·W[n,:] + bih[n]+bhh[n] -
// CTA tile 128m x 128n, BK=16, 256 threads, thread tile 8x8 (4+4 split).
// Double-buffered smem; global loads staged through registers.
__global__ void __launch_bounds__(256) xg_gemm(
    const float* __restrict__ X0, int layer, int K,
    const float* __restrict__ W0, const float* __restrict__ W1,
    const float* __restrict__ bi0, const float* __restrict__ bh0,
    const float* __restrict__ bi1, const float* __restrict__ bh1)
{
    const int M = Bb * Tt;
    __shared__ float Xs[2][16][132];
    __shared__ float Ws[2][16][132];
    const float* X  = layer ? g_h0 : X0;
    const int dir   = blockIdx.z;
    const float* W  = dir ? W1 : W0;
    const float* bi = dir ? bi1 : bi0;
    const float* bh = dir ? bh1 : bh0;
    const int m0 = blockIdx.x * 128;
    const int n0 = blockIdx.y * 128;
    const int tid = threadIdx.x;
    const int tx = tid & 15, ty = tid >> 4;
    const int gr = tid & 127, qh = tid >> 7;   // global-load row, k-half

    const float* Xp = X + (size_t)(m0 + gr) * K + 8 * qh;
    const float* Wp = W + (size_t)(n0 + gr) * K + 8 * qh;

    float4 xr0 = *(const float4*)Xp, xr1 = *(const float4*)(Xp + 4);
    float4 wr0 = *(const float4*)Wp, wr1 = *(const float4*)(Wp + 4);
    const int kq = 8 * qh;
    Xs[0][kq+0][gr]=xr0.x; Xs[0][kq+1][gr]=xr0.y; Xs[0][kq+2][gr]=xr0.z; Xs[0][kq+3][gr]=xr0.w;
    Xs[0][kq+4][gr]=xr1.x; Xs[0][kq+5][gr]=xr1.y; Xs[0][kq+6][gr]=xr1.z; Xs[0][kq+7][gr]=xr1.w;
    Ws[0][kq+0][gr]=wr0.x; Ws[0][kq+1][gr]=wr0.y; Ws[0][kq+2][gr]=wr0.z; Ws[0][kq+3][gr]=wr0.w;
    Ws[0][kq+4][gr]=wr1.x; Ws[0][kq+5][gr]=wr1.y; Ws[0][kq+6][gr]=wr1.z; Ws[0][kq+7][gr]=wr1.w;
    __syncthreads();

    ull acc[8][4];
#pragma unroll
    for (int i = 0; i < 8; i++)
#pragma unroll
        for (int j = 0; j < 4; j++) acc[i][j] = 0ull;

    const int NIT = K / 16;
    for (int it = 0; it < NIT; ++it) {
        const int cur = it & 1;
        if (it + 1 < NIT) {
            const float* xp = Xp + (it + 1) * 16;
            const float* wp = Wp + (it + 1) * 16;
            xr0 = *(const float4*)xp; xr1 = *(const float4*)(xp + 4);
            wr0 = *(const float4*)wp; wr1 = *(const float4*)(wp + 4);
        }
#pragma unroll
        for (int k = 0; k < 16; ++k) {
            float4 xa = *(const float4*)&Xs[cur][k][ty * 4];
            float4 xb = *(const float4*)&Xs[cur][k][64 + ty * 4];
            float4 wa = *(const float4*)&Ws[cur][k][tx * 4];
            float4 wb = *(const float4*)&Ws[cur][k][64 + tx * 4];
            ull p0 = pk2(wa.x, wa.y), p1 = pk2(wa.z, wa.w);
            ull p2 = pk2(wb.x, wb.y), p3 = pk2(wb.z, wb.w);
            ull a;
            a = pk2(xa.x, xa.x);
            fma2(acc[0][0],a,p0); fma2(acc[0][1],a,p1); fma2(acc[0][2],a,p2); fma2(acc[0][3],a,p3);
            a = pk2(xa.y, xa.y);
            fma2(acc[1][0],a,p0); fma2(acc[1][1],a,p1); fma2(acc[1][2],a,p2); fma2(acc[1][3],a,p3);
            a = pk2(xa.z, xa.z);
            fma2(acc[2][0],a,p0); fma2(acc[2][1],a,p1); fma2(acc[2][2],a,p2); fma2(acc[2][3],a,p3);
            a = pk2(xa.w, xa.w);
            fma2(acc[3][0],a,p0); fma2(acc[3][1],a,p1); fma2(acc[3][2],a,p2); fma2(acc[3][3],a,p3);
            a = pk2(xb.x, xb.x);
            fma2(acc[4][0],a,p0); fma2(acc[4][1],a,p1); fma2(acc[4][2],a,p2); fma2(acc[4][3],a,p3);
            a = pk2(xb.y, xb.y);
            fma2(acc[5][0],a,p0); fma2(acc[5][1],a,p1); fma2(acc[5][2],a,p2); fma2(acc[5][3],a,p3);
            a = pk2(xb.z, xb.z);
            fma2(acc[6][0],a,p0); fma2(acc[6][1],a,p1); fma2(acc[6][2],a,p2); fma2(acc[6][3],a,p3);
            a = pk2(xb.w, xb.w);
            fma2(acc[7][0],a,p0); fma2(acc[7][1],a,p1); fma2(acc[7][2],a,p2); fma2(acc[7][3],a,p3);
        }
        if (it + 1 < NIT) {
            const int nxt = cur ^ 1;
            Xs[nxt][kq+0][gr]=xr0.x; Xs[nxt][kq+1][gr]=xr0.y; Xs[nxt][kq+2][gr]=xr0.z; Xs[nxt][kq+3][gr]=xr0.w;
            Xs[nxt][kq+4][gr]=xr1.x; Xs[nxt][kq+5][gr]=xr1.y; Xs[nxt][kq+6][gr]=xr1.z; Xs[nxt][kq+7][gr]=xr1.w;
            Ws[nxt][kq+0][gr]=wr0.x; Ws[nxt][kq+1][gr]=wr0.y; Ws[nxt][kq+2][gr]=wr0.z; Ws[nxt][kq+3][gr]=wr0.w;
            Ws[nxt][kq+4][gr]=wr1.x; Ws[nxt][kq+5][gr]=wr1.y; Ws[nxt][kq+6][gr]=wr1.z; Ws[nxt][kq+7][gr]=wr1.w;
        }
        __syncthreads();
    }

    const int na = n0 + tx * 4, nb = na + 64;
    float bsA[4], bsB[4];
#pragma unroll
    for (int j = 0; j < 4; j++) {
        bsA[j] = bi[na + j] + bh[na + j];
        bsB[j] = bi[nb + j] + bh[nb + j];
    }
    float* base = g_xg + (size_t)dir * M * GH;
#pragma unroll
    for (int i = 0; i < 8; ++i) {
        const int m = m0 + (i < 4 ? ty * 4 + i : 64 + ty * 4 + (i - 4));
        float* y = base + (size_t)m * GH;
        float4 v;
        unpk2(acc[i][0], v.x, v.y); unpk2(acc[i][1], v.z, v.w);
        v.x += bsA[0]; v.y += bsA[1]; v.z += bsA[2]; v.w += bsA[3];
        *(float4*)(y + na) = v;
        unpk2(acc[i][2], v.x, v.y); unpk2(acc[i][3], v.z, v.w);
        v.x += bsB[0]; v.y += bsB[1]; v.z += bsB[2]; v.w += bsB[3];
        *(float4*)(y + nb) = v;
    }
}

// ---------------- LSTM recurrence: one CTA = (direction, 4 batch samples) --
// 512 threads; thread tid owns gate row tid (of 512) for all NB batches.
// smem: all 512 weight rows, cols [0,96) @ stride 100 (204.8 KB)
//       + h[k][b] (2 KB) + gates G[b][4H] (8 KB). Cols [96,128) in registers.
__global__ void __launch_bounds__(512, 1) lstm_rec(
    int layer,
    const float* __restrict__ Wf, const float* __restrict__ Wr)
{
    extern __shared__ float sm[];
    float* sW = sm;                       // 512 * WSTR floats
    float* hs = sm + GH * WSTR;           // [128][NB]
    float* Gs = hs + NB * Hh;             // [NB][512]

    const int dir = blockIdx.y;
    const int b0  = blockIdx.x * NB;
    const float* Whh = dir ? Wr : Wf;
    float* hout = layer ? g_h1 : g_h0;
    const float* xg = g_xg + (size_t)dir * Bb * Tt * GH;
    const int tid  = threadIdx.x;
    const int lane = tid & 31, wid = tid >> 5;

    // --- load weights: cols [0,96) of every row into smem (coalesced by row),
    //     cols [96,128) of this thread's own row into registers ---
    {
        const float4* src = (const float4*)Whh;   // 32 float4 per row
        for (int r = wid; r < GH; r += 16)
            if (lane < 24)
                *(float4*)(sW + r * WSTR + lane * 4) = src[r * 32 + lane];
        for (int i = tid; i < NB * Hh; i += 512) hs[i] = 0.f;
    }
    float4 wreg[8];
    {
        const float4* src = (const float4*)(Whh + (size_t)tid * Hh);
#pragma unroll
        for (int j = 0; j < 8; ++j) wreg[j] = src[24 + j];
    }
    float c0 = 0.f;                       // cell state (one (b,j) per thread)
    const float* wrow = sW + tid * WSTR;
    const int bu = tid >> 7, ju = tid & 127;
    float* hp = hout + (size_t)(b0 + bu) * Tt * (2 * Hh) + dir * Hh + ju;
    __syncthreads();

    const size_t TG = (size_t)Tt * GH;
    for (int s = 0; s < Tt; ++s) {
        const int t = dir ? (Tt - 1 - s) : s;
        const size_t xb = (size_t)b0 * TG + (size_t)t * GH + tid;
        // prefetch xg for this gate row, all 4 batches
        float x0 = xg[xb];
        float x1 = xg[xb + TG];
        float x2 = xg[xb + 2 * TG];
        float x3 = xg[xb + 3 * TG];

        // 4 independent accumulator chains, fully unrolled
        ull aL01 = 0, aL23 = 0, aH01 = 0, aH23 = 0;
#pragma unroll
        for (int k = 0; k < 64; k += 4) {
            float4 wv = *(const float4*)(wrow + k);
#pragma unroll
            for (int kk = 0; kk < 4; ++kk) {
                float4 hv = *(const float4*)(hs + 4 * (k + kk));
                ull h01 = pk2(hv.x, hv.y), h23 = pk2(hv.z, hv.w);
                float w1 = f4c(wv, kk);
                ull a2 = pk2(w1, w1);
                fma2(aL01, a2, h01); fma2(aL23, a2, h23);
            }
        }
#pragma unroll
        for (int k = 64; k < KS; k += 4) {
            float4 wv = *(const float4*)(wrow + k);
#pragma unroll
            for (int kk = 0; kk < 4; ++kk) {
                float4 hv = *(const float4*)(hs + 4 * (k + kk));
                ull h01 = pk2(hv.x, hv.y), h23 = pk2(hv.z, hv.w);
                float w1 = f4c(wv, kk);
                ull a2 = pk2(w1, w1);
                fma2(aH01, a2, h01); fma2(aH23, a2, h23);
            }
        }
#pragma unroll
        for (int j = 0; j < 8; ++j) {
            float4 wv = wreg[j];
            const int k = KS + 4 * j;
#pragma unroll
            for (int kk = 0; kk < 4; ++kk) {
                float4 hv = *(const float4*)(hs + 4 * (k + kk));
                ull h01 = pk2(hv.x, hv.y), h23 = pk2(hv.z, hv.w);
                float w1 = f4c(wv, kk);
                ull a2 = pk2(w1, w1);
                fma2(aH01, a2, h01); fma2(aH23, a2, h23);
            }
        }
        ull a01 = add2(aL01, aH01), a23 = add2(aL23, aH23);

        float a0, a1, a2f, a3f;
        unpk2(a01, a0, a1); unpk2(a23, a2f, a3f);
        Gs[tid]          = a0  + x0;
        Gs[GH + tid]     = a1  + x1;
        Gs[2 * GH + tid] = a2f + x2;
        Gs[3 * GH + tid] = a3f + x3;
        __syncthreads();

        // elementwise update: thread owns (bu, ju)
        {
            const float* G = Gs + bu * GH;
            float ii = G[ju], ff = G[Hh + ju], gg = G[2 * Hh + ju], oo = G[3 * Hh + ju];
            c0 = sigf(ff) * c0 + sigf(ii) * tanhfast(gg);
            float h = sigf(oo) * tanhfast(c0);
            hs[ju * NB + bu] = h;
            hp[(size_t)t * (2 * Hh)] = h;
        }
        __syncthreads();
    }
}

// ---------------- FC head: out[b] = relu(last@fc1^T+b1) @ fc2^T + b2 -------
__global__ void __launch_bounds__(128) fc_head(
    const float* __restrict__ fc1w, const float* __restrict__ fc1b,
    const float* __restrict__ fc2w, const float* __restrict__ fc2b,
    float* __restrict__ out)
{
    __shared__ float last[2 * Hh];
    __shared__ float red[Hh];
    const int b = blockIdx.x, tid = threadIdx.x;
    const float* src = g_h1 + ((size_t)b * Tt + (Tt - 1)) * (2 * Hh);
    last[tid] = src[tid];
    last[tid + Hh] = src[tid + Hh];
    __syncthreads();
    float s = fc1b[tid];
    const float* wr = fc1w + tid * (2 * Hh);
#pragma unroll 8
    for (int k = 0; k < 2 * Hh; ++k) s += wr[k] * last[k];
    red[tid] = fmaxf(s, 0.f) * fc2w[tid];
    __syncthreads();
    for (int st = 64; st > 0; st >>= 1) {
        if (tid < st) red[tid] += red[tid + st];
        __syncthreads();
    }
    if (tid == 0) out[b] = red[0] + fc2b[0];
}

// ---------------- launch ---------------------------------------------------
extern "C" void kernel_launch(void* const* d_in, const int* in_sizes, int n_in,
                              void* d_out, int out_size)
{
    (void)in_sizes; (void)n_in; (void)out_size;
    const float* x     = (const float*)d_in[0];
    const float* Wih0  = (const float*)d_in[1];
    const float* Whh0  = (const float*)d_in[2];
    const float* bih0  = (const float*)d_in[3];
    const float* bhh0  = (const float*)d_in[4];
    const float* Wih0r = (const float*)d_in[5];
    const float* Whh0r = (const float*)d_in[6];
    const float* bih0r = (const float*)d_in[7];
    const float* bhh0r = (const float*)d_in[8];
    const float* Wih1  = (const float*)d_in[9];
    const float* Whh1  = (const float*)d_in[10];
    const float* bih1  = (const float*)d_in[11];
    const float* bhh1  = (const float*)d_in[12];
    const float* Wih1r = (const float*)d_in[13];
    const float* Whh1r = (const float*)d_in[14];
    const float* bih1r = (const float*)d_in[15];
    const float* bhh1r = (const float*)d_in[16];
    const float* fc1w  = (const float*)d_in[17];
    const float* fc1b  = (const float*)d_in[18];
    const float* fc2w  = (const float*)d_in[19];
    const float* fc2b  = (const float*)d_in[20];
    float* out = (float*)d_out;

    const int SMEM = (GH * WSTR + NB * Hh + NB * GH) * 4;   // 215,040 B
    cudaFuncSetAttribute(lstm_rec, cudaFuncAttributeMaxDynamicSharedMemorySize, SMEM);

    dim3 gg(Bb * Tt / 128, GH / 128, 2);
    dim3 gr(Bb / NB, 2);

    // layer 0
    xg_gemm<<<gg, 256>>>(x, 0, Ii, Wih0, Wih0r, bih0, bhh0, bih0r, bhh0r);
    lstm_rec<<<gr, 512, SMEM>>>(0, Whh0, Whh0r);
    // layer 1 (input = g_h0, K = 256)
    xg_gemm<<<gg, 256>>>(x, 1, 2 * Hh, Wih1, Wih1r, bih1, bhh1, bih1r, bhh1r);
    lstm_rec<<<gr, 512, SMEM>>>(1, Whh1, Whh1r);
    // head
    fc_head<<<Bb, Hh>>>(fc1w, fc1b, fc2w, fc2b, out);
}